// round 1
// baseline (speedup 1.0000x reference)
#include <cuda_runtime.h>
#include <math.h>

#define N_ENT 20000
#define DIM   200
#define RR    20
#define NB    20
#define NL    2
#define NT    2
#define NE    250000
#define NQ    8192
#define HID   256
#define D3    600

#define BM 128
#define EGRID 1973                 // ceil((NE + RR*127)/128)
#define EPADTOT (EGRID*BM)         // 252544

// ---------------- device scratch (static; no allocations) ----------------
__device__ __align__(16) float g_relw[NL*RR*DIM*DIM];
__device__ __align__(16) float g_h  [N_ENT*DIM];
__device__ __align__(16) float g_xa [N_ENT*DIM];
__device__ __align__(16) float g_xb [N_ENT*DIM];
__device__ __align__(16) float g_agg[N_ENT*DIM];
__device__ __align__(16) float g_xW [N_ENT*D3];
__device__ __align__(16) float g_hU [N_ENT*D3];
__device__ float g_deg[N_ENT];
__device__ float g_deginv[N_ENT];
__device__ int   g_perm[EPADTOT];
__device__ int   g_cnt[RR];
__device__ int   g_cur[RR];

// ---------------- small utility kernels ----------------
__global__ void k_zerof(float* p, int n) {
    int i = blockIdx.x*blockDim.x + threadIdx.x;
    for (; i < n; i += gridDim.x*blockDim.x) p[i] = 0.f;
}
__global__ void k_filli(int* p, int n, int v) {
    int i = blockIdx.x*blockDim.x + threadIdx.x;
    for (; i < n; i += gridDim.x*blockDim.x) p[i] = v;
}
__global__ void k_copy(float* dst, const float* src, int n) {
    int i = blockIdx.x*blockDim.x + threadIdx.x;
    for (; i < n; i += gridDim.x*blockDim.x) dst[i] = src[i];
}

// relw[l][r][i][o] = sum_b coeff[l][r][b]*basis[l][b][i][o]
__global__ void k_relw(const float* __restrict__ basis, const float* __restrict__ coeff) {
    __shared__ float s_co[NL*RR*NB];
    int tid = threadIdx.x;
    for (int i = tid; i < NL*RR*NB; i += blockDim.x) s_co[i] = coeff[i];
    __syncthreads();
    int gid = blockIdx.x*blockDim.x + tid;
    if (gid >= NL*DIM*DIM) return;
    int l = gid / (DIM*DIM);
    int rem = gid % (DIM*DIM);
    int i = rem / DIM, o = rem % DIM;
    float acc[RR];
#pragma unroll
    for (int r = 0; r < RR; ++r) acc[r] = 0.f;
    for (int b = 0; b < NB; ++b) {
        float bv = basis[((l*NB + b)*DIM + i)*DIM + o];
#pragma unroll
        for (int r = 0; r < RR; ++r) acc[r] += s_co[(l*RR + r)*NB + b] * bv;
    }
    for (int r = 0; r < RR; ++r)
        g_relw[((l*RR + r)*DIM + i)*DIM + o] = acc[r];
}

__global__ void k_deg_acc(const int* __restrict__ rcv) {
    int i = blockIdx.x*blockDim.x + threadIdx.x;
    for (; i < NE; i += gridDim.x*blockDim.x) atomicAdd(&g_deg[rcv[i]], 1.f);
}
__global__ void k_deginv() {
    int i = blockIdx.x*blockDim.x + threadIdx.x;
    if (i < N_ENT) g_deginv[i] = 1.f / fmaxf(g_deg[i], 1.f);
}

__global__ void k_hist(const int* __restrict__ rel) {
    __shared__ int s_cnt[RR];
    int tid = threadIdx.x;
    if (tid < RR) s_cnt[tid] = 0;
    __syncthreads();
    int i = blockIdx.x*blockDim.x + tid;
    for (; i < NE; i += gridDim.x*blockDim.x) atomicAdd(&s_cnt[rel[i]], 1);
    __syncthreads();
    if (tid < RR) atomicAdd(&g_cnt[tid], s_cnt[tid]);
}
__global__ void k_scan() {
    int run = 0;
    for (int r = 0; r < RR; ++r) {
        g_cur[r] = run;
        run += ((g_cnt[r] + BM - 1) / BM) * BM;  // pad each segment to BM
    }
}
__global__ void k_scatter(const int* __restrict__ rel) {
    int i = blockIdx.x*blockDim.x + threadIdx.x;
    for (; i < NE; i += gridDim.x*blockDim.x) {
        int r = rel[i];
        int p = atomicAdd(&g_cur[r], 1);
        g_perm[p] = i;
    }
}

__device__ __forceinline__ void red4(float* p, float a, float b, float c, float d) {
    asm volatile("red.global.add.v4.f32 [%0], {%1,%2,%3,%4};"
                 :: "l"(p), "f"(a), "f"(b), "f"(c), "f"(d) : "memory");
}

// agg[rcv[e]] += x[snd[e]] @ W_rel  (edges relation-sorted, BM-per-block, uniform rel)
__global__ void __launch_bounds__(256)
k_edge_gemm(const float* __restrict__ x, const float* __restrict__ relw_l,
            const int* __restrict__ snd, const int* __restrict__ rcv,
            const int* __restrict__ relt) {
    __shared__ float As[16][BM];
    __shared__ float Bs[16][BM];
    __shared__ int s_src[BM], s_rcv[BM];
    __shared__ int s_rel;
    int tid = threadIdx.x;
    if (tid == 0) s_rel = -1;
    __syncthreads();
    if (tid < BM) {
        int e = g_perm[blockIdx.x*BM + tid];
        int sv = -1, rv = -1;
        if (e >= 0) { sv = snd[e]; rv = rcv[e]; s_rel = relt[e]; }
        s_src[tid] = sv; s_rcv[tid] = rv;
    }
    __syncthreads();
    int rel = s_rel;
    if (rel < 0) return;
    const float* W = relw_l + (size_t)rel * DIM * DIM;
    int n0 = blockIdx.y * BM;
    int tx = tid & 15, ty = tid >> 4;
    float acc[8][8];
#pragma unroll
    for (int i = 0; i < 8; ++i)
#pragma unroll
        for (int j = 0; j < 8; ++j) acc[i][j] = 0.f;

    for (int kt = 0; kt < 13; ++kt) {
        int k0 = kt * 16;
        // A: gathered rows, stored transposed As[k][m]
        for (int s = tid; s < 512; s += 256) {
            int m = s >> 2, kq = (s & 3) * 4;
            float4 v = make_float4(0.f,0.f,0.f,0.f);
            int src = s_src[m];
            if (src >= 0 && k0 + kq < DIM)
                v = *(const float4*)(x + (size_t)src*DIM + k0 + kq);
            As[kq+0][m] = v.x; As[kq+1][m] = v.y; As[kq+2][m] = v.z; As[kq+3][m] = v.w;
        }
        // B: W[k][n]
        for (int s = tid; s < 512; s += 256) {
            int kr = s >> 5, c4 = (s & 31) * 4;
            float4 v = make_float4(0.f,0.f,0.f,0.f);
            int gk = k0 + kr, gc = n0 + c4;
            if (gk < DIM && gc < DIM)
                v = *(const float4*)(W + (size_t)gk*DIM + gc);
            *(float4*)&Bs[kr][c4] = v;
        }
        __syncthreads();
#pragma unroll
        for (int kk = 0; kk < 16; ++kk) {
            float4 a0 = *(const float4*)&As[kk][ty*8];
            float4 a1 = *(const float4*)&As[kk][ty*8+4];
            float4 b0 = *(const float4*)&Bs[kk][tx*8];
            float4 b1 = *(const float4*)&Bs[kk][tx*8+4];
            float a[8] = {a0.x,a0.y,a0.z,a0.w,a1.x,a1.y,a1.z,a1.w};
            float b[8] = {b0.x,b0.y,b0.z,b0.w,b1.x,b1.y,b1.z,b1.w};
#pragma unroll
            for (int i = 0; i < 8; ++i)
#pragma unroll
                for (int j = 0; j < 8; ++j) acc[i][j] += a[i]*b[j];
        }
        __syncthreads();
    }
    // scatter-add (vector atomics)
    int n = n0 + tx*8;
    if (n >= DIM) return;
#pragma unroll
    for (int i = 0; i < 8; ++i) {
        int m = ty*8 + i;
        int rv = s_rcv[m];
        if (rv < 0) continue;
        float* p = g_agg + (size_t)rv*DIM + n;
        red4(p,   acc[i][0], acc[i][1], acc[i][2], acc[i][3]);
        red4(p+4, acc[i][4], acc[i][5], acc[i][6], acc[i][7]);
    }
}

// generic f32 GEMM C = A(MxK) @ B(KxN); epi==1: C=relu(C + aux*deginv[row] + bias[col]) (N==DIM)
__global__ void __launch_bounds__(256)
k_gemm(const float* __restrict__ A, const float* __restrict__ B, float* __restrict__ C,
       int M, int N, int K, int epi,
       const float* __restrict__ aux, const float* __restrict__ dinv,
       const float* __restrict__ bias) {
    __shared__ float As[16][BM];
    __shared__ float Bs[16][BM];
    int tid = threadIdx.x;
    int m0 = blockIdx.x * BM;
    int n0 = blockIdx.y * BM;
    int tx = tid & 15, ty = tid >> 4;
    float acc[8][8];
#pragma unroll
    for (int i = 0; i < 8; ++i)
#pragma unroll
        for (int j = 0; j < 8; ++j) acc[i][j] = 0.f;

    int ktiles = (K + 15) / 16;
    for (int kt = 0; kt < ktiles; ++kt) {
        int k0 = kt * 16;
        for (int s = tid; s < 512; s += 256) {
            int m = s >> 2, kq = (s & 3) * 4;
            float4 v = make_float4(0.f,0.f,0.f,0.f);
            int gm = m0 + m;
            if (gm < M && k0 + kq < K)
                v = *(const float4*)(A + (size_t)gm*K + k0 + kq);
            As[kq+0][m] = v.x; As[kq+1][m] = v.y; As[kq+2][m] = v.z; As[kq+3][m] = v.w;
        }
        for (int s = tid; s < 512; s += 256) {
            int kr = s >> 5, c4 = (s & 31) * 4;
            float4 v = make_float4(0.f,0.f,0.f,0.f);
            int gk = k0 + kr, gc = n0 + c4;
            if (gk < K && gc < N)
                v = *(const float4*)(B + (size_t)gk*N + gc);
            *(float4*)&Bs[kr][c4] = v;
        }
        __syncthreads();
#pragma unroll
        for (int kk = 0; kk < 16; ++kk) {
            float4 a0 = *(const float4*)&As[kk][ty*8];
            float4 a1 = *(const float4*)&As[kk][ty*8+4];
            float4 b0 = *(const float4*)&Bs[kk][tx*8];
            float4 b1 = *(const float4*)&Bs[kk][tx*8+4];
            float a[8] = {a0.x,a0.y,a0.z,a0.w,a1.x,a1.y,a1.z,a1.w};
            float b[8] = {b0.x,b0.y,b0.z,b0.w,b1.x,b1.y,b1.z,b1.w};
#pragma unroll
            for (int i = 0; i < 8; ++i)
#pragma unroll
                for (int j = 0; j < 8; ++j) acc[i][j] += a[i]*b[j];
        }
        __syncthreads();
    }
#pragma unroll
    for (int i = 0; i < 8; ++i) {
        int row = m0 + ty*8 + i;
        if (row >= M) continue;
#pragma unroll
        for (int j = 0; j < 8; ++j) {
            int col = n0 + tx*8 + j;
            if (col >= N) continue;
            float v = acc[i][j];
            if (epi == 1) {
                v += aux[(size_t)row*DIM + col] * dinv[row] + bias[col];
                v = fmaxf(v, 0.f);
            }
            C[(size_t)row*N + col] = v;
        }
    }
}

__device__ __forceinline__ float sigf(float x) { return 1.f / (1.f + expf(-x)); }

__global__ void k_gru(const float* __restrict__ bg) {
    int idx = blockIdx.x*blockDim.x + threadIdx.x;
    if (idx >= N_ENT*DIM) return;
    int n = idx / DIM, c = idx % DIM;
    size_t b = (size_t)n*D3;
    float r  = sigf(g_xW[b + c]        + g_hU[b + c]        + bg[c]);
    float z  = sigf(g_xW[b + DIM + c]  + g_hU[b + DIM + c]  + bg[DIM + c]);
    float hu3 = g_hU[b + 2*DIM + c];
    float ht = tanhf(g_xW[b + 2*DIM + c] + hu3 + bg[2*DIM + c] + r * hu3);
    float h0 = g_h[idx];
    g_h[idx] = (1.f - z)*h0 + z*ht;
}

// scorer: out[q] = relu([h_s, rel, h_o] @ fc1 + b1) @ fc2 + b2
__global__ void __launch_bounds__(256)
k_score(const int* __restrict__ triples, const float* __restrict__ rel_emb,
        const float* __restrict__ fc1, const float* __restrict__ b1,
        const float* __restrict__ fc2, const float* __restrict__ fc2b,
        float* __restrict__ out) {
    __shared__ float As[32][8];
    __shared__ float Bs[8][HID];
    __shared__ int s_s[32], s_r[32], s_o[32];
    int tid = threadIdx.x;
    int qbase = blockIdx.x * 32;
    if (tid < 32) {
        s_s[tid] = triples[(qbase + tid)*3 + 0];
        s_r[tid] = triples[(qbase + tid)*3 + 1];
        s_o[tid] = triples[(qbase + tid)*3 + 2];
    }
    __syncthreads();
    int w = tid >> 5, lane = tid & 31;
    float acc[4][8];
#pragma unroll
    for (int i = 0; i < 4; ++i)
#pragma unroll
        for (int j = 0; j < 8; ++j) acc[i][j] = 0.f;

    for (int k0 = 0; k0 < D3; k0 += 8) {
        {   // gather A: one element per thread
            int qi = tid >> 3, kk = tid & 7, k = k0 + kk;
            float v;
            if (k < DIM)            v = g_h[(size_t)s_s[qi]*DIM + k];
            else if (k < 2*DIM)     v = rel_emb[(size_t)s_r[qi]*DIM + (k - DIM)];
            else                    v = g_h[(size_t)s_o[qi]*DIM + (k - 2*DIM)];
            As[qi][kk] = v;
        }
        {   // B tile
            int kr = tid >> 5, cb = tid & 31;
#pragma unroll
            for (int j = 0; j < 8; ++j)
                Bs[kr][cb + 32*j] = fc1[(size_t)(k0 + kr)*HID + cb + 32*j];
        }
        __syncthreads();
#pragma unroll
        for (int kk = 0; kk < 8; ++kk) {
#pragma unroll
            for (int i = 0; i < 4; ++i) {
                float a = As[w*4 + i][kk];
#pragma unroll
                for (int j = 0; j < 8; ++j)
                    acc[i][j] += a * Bs[kk][lane + 32*j];
            }
        }
        __syncthreads();
    }
#pragma unroll
    for (int i = 0; i < 4; ++i) {
        float p = 0.f;
#pragma unroll
        for (int j = 0; j < 8; ++j) {
            int col = lane + 32*j;
            float hv = fmaxf(acc[i][j] + b1[col], 0.f);
            p += hv * fc2[col];
        }
#pragma unroll
        for (int off = 16; off > 0; off >>= 1)
            p += __shfl_down_sync(0xffffffffu, p, off);
        if (lane == 0) out[qbase + w*4 + i] = p + fc2b[0];
    }
}

// ---------------- host ----------------
extern "C" void kernel_launch(void* const* d_in, const int* in_sizes, int n_in,
                              void* d_out, int out_size) {
    const float* entity_emb = (const float*)d_in[0];
    const float* basis      = (const float*)d_in[1];
    const float* coeff      = (const float*)d_in[2];
    const float* self_w     = (const float*)d_in[3];
    const float* bias       = (const float*)d_in[4];
    const float* W_gates    = (const float*)d_in[5];
    const float* U_gates    = (const float*)d_in[6];
    const float* b_gates    = (const float*)d_in[7];
    const float* rel_emb    = (const float*)d_in[8];
    const float* fc1        = (const float*)d_in[9];
    const float* fc1_b      = (const float*)d_in[10];
    const float* fc2        = (const float*)d_in[11];
    const float* fc2_b      = (const float*)d_in[12];
    const int*   senders    = (const int*)d_in[13];
    const int*   receivers  = (const int*)d_in[14];
    const int*   rel_types  = (const int*)d_in[15];
    const int*   triples    = (const int*)d_in[16];
    float* out = (float*)d_out;

    float *p_relw, *p_h, *p_xa, *p_xb, *p_agg, *p_xW, *p_hU, *p_deg, *p_dinv;
    int *p_perm, *p_cnt;
    cudaGetSymbolAddress((void**)&p_relw, g_relw);
    cudaGetSymbolAddress((void**)&p_h,    g_h);
    cudaGetSymbolAddress((void**)&p_xa,   g_xa);
    cudaGetSymbolAddress((void**)&p_xb,   g_xb);
    cudaGetSymbolAddress((void**)&p_agg,  g_agg);
    cudaGetSymbolAddress((void**)&p_xW,   g_xW);
    cudaGetSymbolAddress((void**)&p_hU,   g_hU);
    cudaGetSymbolAddress((void**)&p_deg,  g_deg);
    cudaGetSymbolAddress((void**)&p_dinv, g_deginv);
    cudaGetSymbolAddress((void**)&p_perm, g_perm);
    cudaGetSymbolAddress((void**)&p_cnt,  g_cnt);

    k_relw<<<(NL*DIM*DIM + 255)/256, 256>>>(basis, coeff);
    k_copy<<<1024, 256>>>(p_h, entity_emb, N_ENT*DIM);

    for (int t = 0; t < NT; ++t) {
        const int* snd = senders   + (size_t)t*NE;
        const int* rcv = receivers + (size_t)t*NE;
        const int* rlt = rel_types + (size_t)t*NE;

        k_zerof<<<256, 256>>>(p_deg, N_ENT);
        k_deg_acc<<<512, 256>>>(rcv);
        k_deginv<<<(N_ENT + 255)/256, 256>>>();

        k_filli<<<512, 256>>>(p_perm, EPADTOT, -1);
        k_filli<<<1, 32>>>(p_cnt, RR, 0);
        k_hist<<<256, 256>>>(rlt);
        k_scan<<<1, 1>>>();
        k_scatter<<<512, 256>>>(rlt);

        k_copy<<<1024, 256>>>(p_xa, p_h, N_ENT*DIM);
        float* xin = p_xa;
        for (int l = 0; l < NL; ++l) {
            float* xout = (l == 0) ? p_xb : p_xa;
            k_zerof<<<1024, 256>>>(p_agg, N_ENT*DIM);
            k_edge_gemm<<<dim3(EGRID, 2), 256>>>(xin, p_relw + (size_t)l*RR*DIM*DIM,
                                                 snd, rcv, rlt);
            k_gemm<<<dim3((N_ENT + BM - 1)/BM, (DIM + BM - 1)/BM), 256>>>(
                xin, self_w + (size_t)l*DIM*DIM, xout,
                N_ENT, DIM, DIM, 1, p_agg, p_dinv, bias + (size_t)l*DIM);
            xin = xout;
        }
        // xin == p_xa here (final layer output)
        k_gemm<<<dim3((N_ENT + BM - 1)/BM, (D3 + BM - 1)/BM), 256>>>(
            xin, W_gates, p_xW, N_ENT, D3, DIM, 0, nullptr, nullptr, nullptr);
        k_gemm<<<dim3((N_ENT + BM - 1)/BM, (D3 + BM - 1)/BM), 256>>>(
            p_h, U_gates, p_hU, N_ENT, D3, DIM, 0, nullptr, nullptr, nullptr);
        k_gru<<<(N_ENT*DIM + 255)/256, 256>>>(b_gates);
    }

    k_score<<<NQ/32, 256>>>(triples, rel_emb, fc1, fc1_b, fc2, fc2_b, out);
}